// round 2
// baseline (speedup 1.0000x reference)
#include <cuda_runtime.h>

// Problem constants (from reference)
#define BLOCK 256
#define EPT 4
#define TILE (BLOCK * EPT)   // 1024 elements per block

__device__ double g_firing;

__device__ __forceinline__ float limiter(float a, float b) {
    // Reference's where-chain degenerates: idx1 & idx2 is impossible, so w = m always.
    float x1 = fabsf(a + b) * 0.5f;
    float x2 = 2.0f * fminf(fabsf(a), fabsf(b));
    return fminf(x1, x2);
}

__global__ void zero_kernel() { g_firing = 0.0; }

__global__ void __launch_bounds__(BLOCK)
main_kernel(const float* __restrict__ y,
            const float* __restrict__ gsyn_p,
            const float* __restrict__ isyn_p,
            float* __restrict__ out,
            int n)
{
    constexpr float GL    = 0.1f;
    constexpr float EL    = -5.0f;
    constexpr float CMI   = 1.0f / 0.3f;      // 1/Cm
    constexpr float IEXT  = 0.4f;
    constexpr float INV_DTS = 2.0f;           // 1/0.5
    constexpr float COEF  = 0.4f;             // 0.5*(1 - DT/DTS)
    constexpr float ISS   = 0.57735026919f;   // 1/(SIGMA*sqrt(2)) = 1/sqrt(3)
    constexpr float SQ2   = 1.41421356237f;
    constexpr float SQ2PI = 0.7978845608028654f;

    // smem tiles: z[base + k] lives at s[4 + k]; left halo at s[2],s[3]; right halo s[4+TILE]
    __shared__ float ro_raw[TILE + 8];
    __shared__ float V_raw[TILE + 8];
    __shared__ float s_red[BLOCK / 32];

    const float* ro = y;
    const float* V  = y + n;

    const float Isyn    = __ldg(isyn_p);
    const float inv_tau = (GL + __ldg(gsyn_p)) * CMI;   // 1/tau_m

    float* rs = ro_raw + 4;
    float* vs = V_raw + 4;

    const int t     = threadIdx.x;
    const int base  = blockIdx.x * TILE;
    const int i0    = base + 4 * t;

    // ---- load tile (vectorized) ----
    if (i0 + 3 < n) {
        *reinterpret_cast<float4*>(rs + 4 * t) = *reinterpret_cast<const float4*>(ro + i0);
        *reinterpret_cast<float4*>(vs + 4 * t) = *reinterpret_cast<const float4*>(V + i0);
    } else {
        #pragma unroll
        for (int j = 0; j < EPT; j++) {
            int i = i0 + j;
            if (i < n) { rs[4 * t + j] = ro[i]; vs[4 * t + j] = V[i]; }
        }
    }
    if (t == 0) {
        rs[-1] = (base >= 1) ? ro[base - 1] : 0.0f;
        rs[-2] = (base >= 2) ? ro[base - 2] : 0.0f;
        vs[-1] = (base >= 1) ? V[base - 1] : 0.0f;
        vs[-2] = (base >= 2) ? V[base - 2] : 0.0f;
    }
    if (t == 1) {
        int gi = base + TILE;
        rs[TILE] = (gi < n) ? ro[gi] : 0.0f;
        vs[TILE] = (gi < n) ? V[gi] : 0.0f;
    }
    __syncthreads();

    float outr[EPT], outv[EPT];
    float fsum = 0.0f;

    #pragma unroll
    for (int j = 0; j < EPT; j++) {
        const int i  = i0 + j;
        if (i >= n) { outr[j] = 0.0f; outv[j] = 0.0f; continue; }
        const int li = 4 * t + j;

        const float rzm2 = rs[li - 2], rzm1 = rs[li - 1], rz0 = rs[li], rzp1 = rs[li + 1];
        const float vzm2 = vs[li - 2], vzm1 = vs[li - 1], vz0 = vs[li], vzp1 = vs[li + 1];

        // ---- H(V) ----
        const float dVdt = (GL * (EL - vz0) + IEXT + Isyn) * CMI;
        const float T    = fmaxf(-vz0, -1.0f) * ISS;            // VT = 0
        const float T2   = T * T;
        const float A    = __expf(0.0061f + T * (-1.12f + T * (-0.257f + T * (-0.072f + T * (-0.0117f)))));
        const float dTdt = fminf(-dVdt * ISS, 0.0f);
        const float F    = SQ2PI * __expf(-T2) * __frcp_rn(1.00000001f + erff(T));
        const float Hv   = fmaxf(A * inv_tau - SQ2 * dTdt * F, 0.0f);  // (A+B)/tau, B/tau = -SQ2*dTdt*F

        const float srcr = rz0 * Hv;
        fsum += srcr;

        // ---- dro_dt ----
        {
            float dm2 = rzm1 - rzm2, dm1 = rz0 - rzm1, dd0 = rzp1 - rz0;
            float Lm  = (i >= 2) ? limiter(dm1, dm2) : 0.0f;
            float o;
            if (i == 0) {
                o = 0.0f;                                       // fixed up after reduction
            } else if (i == n - 1) {
                o = (rzm1 + COEF * Lm) * INV_DTS - srcr;
            } else {
                float Li = limiter(dd0, dm1);
                o = -(dm1 + COEF * (Li - Lm)) * INV_DTS - srcr;
            }
            outr[j] = o;
        }

        // ---- dV_dt ----
        {
            float dm2 = vzm1 - vzm2, dm1 = vz0 - vzm1, dd0 = vzp1 - vz0;
            float Lm  = (i >= 2) ? limiter(dm1, dm2) : 0.0f;
            float o;
            if (i == 0) {
                o = 0.0f;                                       // dV_dt[0] = 0
            } else if (i == n - 1) {
                o = dVdt;                                       // dV_dt[-1] = dVdt[-1]
            } else {
                float Li = limiter(dd0, dm1);
                o = -(dm1 + COEF * (Li - Lm)) * INV_DTS + dVdt; // src = -dVdt
            }
            outv[j] = o;
        }
    }

    // ---- stores (vectorized) ----
    if (i0 + 3 < n) {
        *reinterpret_cast<float4*>(out + i0)     = make_float4(outr[0], outr[1], outr[2], outr[3]);
        *reinterpret_cast<float4*>(out + n + i0) = make_float4(outv[0], outv[1], outv[2], outv[3]);
    } else {
        #pragma unroll
        for (int j = 0; j < EPT; j++) {
            int i = i0 + j;
            if (i < n) { out[i] = outr[j]; out[n + i] = outv[j]; }
        }
    }

    // ---- firing reduction ----
    #pragma unroll
    for (int off = 16; off > 0; off >>= 1)
        fsum += __shfl_down_sync(0xffffffffu, fsum, off);
    if ((t & 31) == 0) s_red[t >> 5] = fsum;
    __syncthreads();
    if (t < BLOCK / 32) {
        float v = s_red[t];
        #pragma unroll
        for (int off = (BLOCK / 64); off > 0; off >>= 1)
            v += __shfl_down_sync(0xffu, v, off);
        if (t == 0) atomicAdd(&g_firing, (double)v);
    }
}

__global__ void fixup_kernel(const float* __restrict__ y, float* __restrict__ out) {
    // dro_dt[0] = -ro[0]/DTS - src[0],  src[0] = -firing
    out[0] = -y[0] * 2.0f + (float)g_firing;
}

extern "C" void kernel_launch(void* const* d_in, const int* in_sizes, int n_in,
                              void* d_out, int out_size)
{
    // inputs: [0]=t(1), [1]=y(2N), [2]=gsyn(1), [3]=Isyn(1)
    const float* y    = (const float*)d_in[1];
    const float* gsyn = (const float*)d_in[2];
    const float* isyn = (const float*)d_in[3];
    float* out = (float*)d_out;
    const int n = in_sizes[1] / 2;

    const int nblocks = (n + TILE - 1) / TILE;

    zero_kernel<<<1, 1>>>();
    main_kernel<<<nblocks, BLOCK>>>(y, gsyn, isyn, out, n);
    fixup_kernel<<<1, 1>>>(y, out);
}

// round 6
// speedup vs baseline: 1.1146x; 1.1146x over previous
#include <cuda_runtime.h>

#define BLOCK 256
#define EPT 4
#define TILE (BLOCK * EPT)   // 1024 elements per block

__device__ double g_firing;          // zero-initialized at load; restored to 0 each launch
__device__ unsigned int g_count;     // ditto

__device__ __forceinline__ float limiter(float a, float b) {
    // Reference's where-chain degenerates: w = min(|a+b|/2, 2*min(|a|,|b|)) always.
    return fminf(fabsf(a + b) * 0.5f, 2.0f * fminf(fabsf(a), fabsf(b)));
}

__global__ void __launch_bounds__(BLOCK)
main_kernel(const float* __restrict__ y,
            const float* __restrict__ gsyn_p,
            const float* __restrict__ isyn_p,
            float* __restrict__ out,
            int n)
{
    constexpr float GL      = 0.1f;
    constexpr float EL      = -5.0f;
    constexpr float CMI     = 1.0f / 0.3f;       // 1/Cm
    constexpr float IEXT    = 0.4f;
    constexpr float INV_DTS = 2.0f;              // 1/DTS
    constexpr float COEF    = 0.4f;              // 0.5*(1 - DT/DTS)
    constexpr float ISS     = 0.57735026919f;    // 1/(SIGMA*sqrt(2))
    constexpr float SQ2     = 1.41421356237f;
    constexpr float SQ2PI   = 0.7978845608028654f;

    __shared__ float s_red[BLOCK / 32];

    const float* ro = y;
    const float* V  = y + n;

    const float Isyn    = __ldg(isyn_p);
    const float inv_tau = (GL + __ldg(gsyn_p)) * CMI;          // 1/tau_m
    const float C1      = (GL * EL + IEXT + Isyn) * CMI;       // dVdt = C1 - C2*V
    const float C2      = GL * CMI;

    const int t  = threadIdx.x;
    const int i0 = blockIdx.x * TILE + 4 * t;

    float fsum = 0.0f;

    if (i0 >= 2 && i0 + 4 < n) {
        // ---------- interior fast path (branch-free) ----------
        float rv[7], vv[7];
        const float4 r4 = *reinterpret_cast<const float4*>(ro + i0);
        const float4 v4 = *reinterpret_cast<const float4*>(V + i0);
        rv[0] = __ldg(ro + i0 - 2); rv[1] = __ldg(ro + i0 - 1);
        rv[2] = r4.x; rv[3] = r4.y; rv[4] = r4.z; rv[5] = r4.w;
        rv[6] = __ldg(ro + i0 + 4);
        vv[0] = __ldg(V + i0 - 2);  vv[1] = __ldg(V + i0 - 1);
        vv[2] = v4.x; vv[3] = v4.y; vv[4] = v4.z; vv[5] = v4.w;
        vv[6] = __ldg(V + i0 + 4);

        float rd[6], vd[6];
        #pragma unroll
        for (int k = 0; k < 6; k++) { rd[k] = rv[k + 1] - rv[k]; vd[k] = vv[k + 1] - vv[k]; }
        float rL[5], vL[5];
        #pragma unroll
        for (int k = 0; k < 5; k++) { rL[k] = limiter(rd[k + 1], rd[k]); vL[k] = limiter(vd[k + 1], vd[k]); }

        float outr[EPT], outv[EPT];
        #pragma unroll
        for (int j = 0; j < EPT; j++) {
            const float vz0  = vv[j + 2];
            const float dVdt = C1 - C2 * vz0;
            const float T    = fmaxf(-vz0, -1.0f) * ISS;       // VT = 0
            const float A    = __expf(0.0061f + T * (-1.12f + T * (-0.257f + T * (-0.072f + T * (-0.0117f)))));
            const float dTdt = fminf(-dVdt * ISS, 0.0f);
            const float F    = SQ2PI * __expf(-T * T) * __frcp_rn(1.00000001f + erff(T));
            const float Hv   = fmaxf(A * inv_tau - SQ2 * dTdt * F, 0.0f);

            const float srcr = rv[j + 2] * Hv;
            fsum += srcr;

            outr[j] = -(rd[j + 1] + COEF * (rL[j + 1] - rL[j])) * INV_DTS - srcr;
            outv[j] = -(vd[j + 1] + COEF * (vL[j + 1] - vL[j])) * INV_DTS + dVdt;
        }
        *reinterpret_cast<float4*>(out + i0)     = make_float4(outr[0], outr[1], outr[2], outr[3]);
        *reinterpret_cast<float4*>(out + n + i0) = make_float4(outv[0], outv[1], outv[2], outv[3]);
    } else {
        // ---------- boundary slow path (first/last blocks only) ----------
        #pragma unroll
        for (int j = 0; j < EPT; j++) {
            const int i = i0 + j;
            if (i >= n) break;
            const int im2 = max(i - 2, 0), im1 = max(i - 1, 0), ip1 = min(i + 1, n - 1);

            const float rzm2 = __ldg(ro + im2), rzm1 = __ldg(ro + im1);
            const float rz0  = __ldg(ro + i),   rzp1 = __ldg(ro + ip1);
            const float vzm2 = __ldg(V + im2),  vzm1 = __ldg(V + im1);
            const float vz0  = __ldg(V + i),    vzp1 = __ldg(V + ip1);

            const float dVdt = C1 - C2 * vz0;
            const float T    = fmaxf(-vz0, -1.0f) * ISS;
            const float A    = __expf(0.0061f + T * (-1.12f + T * (-0.257f + T * (-0.072f + T * (-0.0117f)))));
            const float dTdt = fminf(-dVdt * ISS, 0.0f);
            const float F    = SQ2PI * __expf(-T * T) * __frcp_rn(1.00000001f + erff(T));
            const float Hv   = fmaxf(A * inv_tau - SQ2 * dTdt * F, 0.0f);

            const float srcr = rz0 * Hv;
            fsum += srcr;

            // dro_dt  (out[0] is written exclusively by the last-finishing block)
            {
                float dm2 = rzm1 - rzm2, dm1 = rz0 - rzm1, dd0 = rzp1 - rz0;
                float Lm  = (i >= 2) ? limiter(dm1, dm2) : 0.0f;
                if (i == n - 1) {
                    out[i] = (rzm1 + COEF * Lm) * INV_DTS - srcr;
                } else if (i != 0) {
                    out[i] = -(dm1 + COEF * (limiter(dd0, dm1) - Lm)) * INV_DTS - srcr;
                }
            }
            // dV_dt
            {
                float dm2 = vzm1 - vzm2, dm1 = vz0 - vzm1, dd0 = vzp1 - vz0;
                float Lm  = (i >= 2) ? limiter(dm1, dm2) : 0.0f;
                float o;
                if (i == 0)           o = 0.0f;
                else if (i == n - 1)  o = dVdt;
                else                  o = -(dm1 + COEF * (limiter(dd0, dm1) - Lm)) * INV_DTS + dVdt;
                out[n + i] = o;
            }
        }
    }

    // ---------- block reduction of firing ----------
    #pragma unroll
    for (int off = 16; off > 0; off >>= 1)
        fsum += __shfl_down_sync(0xffffffffu, fsum, off);
    if ((t & 31) == 0) s_red[t >> 5] = fsum;
    __syncthreads();
    if (t < 32) {
        float v = (t < BLOCK / 32) ? s_red[t] : 0.0f;
        #pragma unroll
        for (int off = 4; off > 0; off >>= 1)
            v += __shfl_down_sync(0xffffffffu, v, off);
        if (t == 0) {
            atomicAdd(&g_firing, (double)v);
            __threadfence();
            unsigned int done = atomicAdd(&g_count, 1u);
            if (done == gridDim.x - 1) {
                // all blocks' g_firing contributions are visible (fence-before-count)
                __threadfence();
                double f = atomicAdd(&g_firing, 0.0);
                // dro_dt[0] = -ro[0]/DTS - src[0],  src[0] = -firing
                out[0] = -2.0f * __ldg(y) + (float)f;
                // restore initial state for the next (graph-replayed) call
                atomicExch(&g_count, 0u);
                atomicExch(reinterpret_cast<unsigned long long*>(&g_firing), 0ull);
            }
        }
    }
}

extern "C" void kernel_launch(void* const* d_in, const int* in_sizes, int n_in,
                              void* d_out, int out_size)
{
    // inputs: [0]=t(1), [1]=y(2N), [2]=gsyn(1), [3]=Isyn(1)
    const float* y    = (const float*)d_in[1];
    const float* gsyn = (const float*)d_in[2];
    const float* isyn = (const float*)d_in[3];
    float* out = (float*)d_out;
    const int n = in_sizes[1] / 2;

    const int nblocks = (n + TILE - 1) / TILE;
    main_kernel<<<nblocks, BLOCK>>>(y, gsyn, isyn, out, n);
}

// round 10
// speedup vs baseline: 1.1452x; 1.0274x over previous
#include <cuda_runtime.h>

#define BLOCK 256
#define EPT 4
#define TILE (BLOCK * EPT)   // 1024 elements per block

__device__ double g_firing;          // zero-initialized at load; restored to 0 each launch
__device__ unsigned int g_count;     // ditto

// Scaled limiter: returns 2*L. Caller folds the 1/2 into COEF2.
// FMNMX takes |src| modifiers, so the abs ops are free.
__device__ __forceinline__ float limiter2(float a, float b) {
    return fminf(fabsf(a + b), 4.0f * fminf(fabsf(a), fabsf(b)));
}

__device__ __forceinline__ float ex2(float x) {   // raw MUFU EX2 (2^x)
    float r;
    asm("ex2.approx.ftz.f32 %0, %1;" : "=f"(r) : "f"(x));
    return r;
}

// H(V): also returns dVdt via reference.
// exp() rewritten as 2^(log2e * .), log2e folded into the coefficients.
// erf via Abramowitz-Stegun 7.1.26, reusing the exp(-T^2) term.
__device__ __forceinline__ float H_of_V(float vz0, float C1, float C2,
                                        float inv_tau, float& dVdt_out)
{
    // A-poly coefficients pre-multiplied by log2(e)
    constexpr float c0 =  0.0088004397f;
    constexpr float c1 = -1.6158184458f;
    constexpr float c2 = -0.3707726255f;
    constexpr float c3 = -0.1038740429f;
    constexpr float c4 = -0.0168795320f;
    constexpr float NL2E = -1.4426950408889634f; // -log2(e)
    constexpr float ISS  = 0.57735026919f;       // 1/(SIGMA*sqrt(2))
    constexpr float ISSK = 0.6514700193f;        // ISS * SQ2 * SQ2PI

    const float dVdt = fmaf(-C2, vz0, C1);
    dVdt_out = dVdt;

    const float T  = fmaxf(-vz0, -1.0f) * ISS;   // VT = 0
    const float e  = ex2(NL2E * (T * T));        // exp(-T^2)

    // A = exp(p(T)) = 2^(c0 + c1 T + c2 T^2 + c3 T^3 + c4 T^4)
    const float A  = ex2(fmaf(T, fmaf(T, fmaf(T, fmaf(T, c4, c3), c2), c1), c0));

    // erf(T) ~ sign(T) * (1 - poly(t) * exp(-T^2)),  t = 1/(1 + 0.3275911 |T|)
    const float tt = __frcp_rn(fmaf(0.3275911f, fabsf(T), 1.0f));
    float poly = fmaf(tt,  1.061405429f, -1.453152027f);
    poly = fmaf(tt, poly,  1.421413741f);
    poly = fmaf(tt, poly, -0.284496736f);
    poly = fmaf(tt, poly,  0.254829592f);
    poly *= tt;
    const float erfT = copysignf(fmaf(-poly, e, 1.0f), T);

    // H = A/tau - SQ2*dTdt*F,  dTdt = min(-dVdt*ISS, 0)
    //   = A*inv_tau + max(dVdt*ISSK, 0) * e / (1.00000001 + erf(T))   [term is ADDED]
    const float D  = 1.00000001f + erfT;
    const float G  = fmaxf(dVdt * ISSK, 0.0f);
    const float Bv = G * e * __frcp_rn(D);

    return fmaxf(fmaf(A, inv_tau, Bv), 0.0f);
}

__global__ void __launch_bounds__(BLOCK)
main_kernel(const float* __restrict__ y,
            const float* __restrict__ gsyn_p,
            const float* __restrict__ isyn_p,
            float* __restrict__ out,
            int n)
{
    constexpr float GL      = 0.1f;
    constexpr float EL      = -5.0f;
    constexpr float CMI     = 1.0f / 0.3f;       // 1/Cm
    constexpr float IEXT    = 0.4f;
    constexpr float INV_DTS = 2.0f;              // 1/DTS
    constexpr float COEF2   = 0.2f;              // 0.5*(1 - DT/DTS) * 0.5  (limiter2 carries 2x)

    __shared__ float s_red[BLOCK / 32];

    const float* ro = y;
    const float* V  = y + n;

    const float Isyn    = __ldg(isyn_p);
    const float inv_tau = (GL + __ldg(gsyn_p)) * CMI;          // 1/tau_m
    const float C1      = (GL * EL + IEXT + Isyn) * CMI;       // dVdt = C1 - C2*V
    const float C2      = GL * CMI;

    const int t  = threadIdx.x;
    const int i0 = blockIdx.x * TILE + 4 * t;

    float fsum = 0.0f;

    if (i0 >= 2 && i0 + 4 < n) {
        // ---------- interior fast path (branch-free) ----------
        float rv[7], vv[7];
        const float4 r4 = *reinterpret_cast<const float4*>(ro + i0);
        const float4 v4 = *reinterpret_cast<const float4*>(V + i0);
        rv[0] = __ldg(ro + i0 - 2); rv[1] = __ldg(ro + i0 - 1);
        rv[2] = r4.x; rv[3] = r4.y; rv[4] = r4.z; rv[5] = r4.w;
        rv[6] = __ldg(ro + i0 + 4);
        vv[0] = __ldg(V + i0 - 2);  vv[1] = __ldg(V + i0 - 1);
        vv[2] = v4.x; vv[3] = v4.y; vv[4] = v4.z; vv[5] = v4.w;
        vv[6] = __ldg(V + i0 + 4);

        float rd[6], vd[6];
        #pragma unroll
        for (int k = 0; k < 6; k++) { rd[k] = rv[k + 1] - rv[k]; vd[k] = vv[k + 1] - vv[k]; }
        float rL[5], vL[5];
        #pragma unroll
        for (int k = 0; k < 5; k++) { rL[k] = limiter2(rd[k + 1], rd[k]); vL[k] = limiter2(vd[k + 1], vd[k]); }

        float outr[EPT], outv[EPT];
        #pragma unroll
        for (int j = 0; j < EPT; j++) {
            float dVdt;
            const float Hv = H_of_V(vv[j + 2], C1, C2, inv_tau, dVdt);

            const float srcr = rv[j + 2] * Hv;
            fsum += srcr;

            outr[j] = fmaf(-INV_DTS, fmaf(COEF2, rL[j + 1] - rL[j], rd[j + 1]), -srcr);
            outv[j] = fmaf(-INV_DTS, fmaf(COEF2, vL[j + 1] - vL[j], vd[j + 1]),  dVdt);
        }
        *reinterpret_cast<float4*>(out + i0)     = make_float4(outr[0], outr[1], outr[2], outr[3]);
        *reinterpret_cast<float4*>(out + n + i0) = make_float4(outv[0], outv[1], outv[2], outv[3]);
    } else {
        // ---------- boundary slow path (first/last blocks only) ----------
        #pragma unroll
        for (int j = 0; j < EPT; j++) {
            const int i = i0 + j;
            if (i >= n) break;
            const int im2 = max(i - 2, 0), im1 = max(i - 1, 0), ip1 = min(i + 1, n - 1);

            const float rzm2 = __ldg(ro + im2), rzm1 = __ldg(ro + im1);
            const float rz0  = __ldg(ro + i),   rzp1 = __ldg(ro + ip1);
            const float vzm2 = __ldg(V + im2),  vzm1 = __ldg(V + im1);
            const float vz0  = __ldg(V + i),    vzp1 = __ldg(V + ip1);

            float dVdt;
            const float Hv = H_of_V(vz0, C1, C2, inv_tau, dVdt);

            const float srcr = rz0 * Hv;
            fsum += srcr;

            // dro_dt  (out[0] is written exclusively by the last-finishing block)
            {
                float dm2 = rzm1 - rzm2, dm1 = rz0 - rzm1, dd0 = rzp1 - rz0;
                float Lm  = (i >= 2) ? limiter2(dm1, dm2) : 0.0f;
                if (i == n - 1) {
                    out[i] = fmaf(INV_DTS, fmaf(COEF2, Lm, rzm1), -srcr);
                } else if (i != 0) {
                    out[i] = fmaf(-INV_DTS, fmaf(COEF2, limiter2(dd0, dm1) - Lm, dm1), -srcr);
                }
            }
            // dV_dt
            {
                float dm2 = vzm1 - vzm2, dm1 = vz0 - vzm1, dd0 = vzp1 - vz0;
                float Lm  = (i >= 2) ? limiter2(dm1, dm2) : 0.0f;
                float o;
                if (i == 0)           o = 0.0f;
                else if (i == n - 1)  o = dVdt;
                else                  o = fmaf(-INV_DTS, fmaf(COEF2, limiter2(dd0, dm1) - Lm, dm1), dVdt);
                out[n + i] = o;
            }
        }
    }

    // ---------- block reduction of firing ----------
    #pragma unroll
    for (int off = 16; off > 0; off >>= 1)
        fsum += __shfl_down_sync(0xffffffffu, fsum, off);
    if ((t & 31) == 0) s_red[t >> 5] = fsum;
    __syncthreads();
    if (t < 32) {
        float v = (t < BLOCK / 32) ? s_red[t] : 0.0f;
        #pragma unroll
        for (int off = 4; off > 0; off >>= 1)
            v += __shfl_down_sync(0xffffffffu, v, off);
        if (t == 0) {
            atomicAdd(&g_firing, (double)v);
            __threadfence();
            unsigned int done = atomicAdd(&g_count, 1u);
            if (done == gridDim.x - 1) {
                __threadfence();
                double f = atomicAdd(&g_firing, 0.0);
                // dro_dt[0] = -ro[0]/DTS - src[0],  src[0] = -firing
                out[0] = fmaf(-2.0f, __ldg(y), (float)f);
                // restore initial state for the next (graph-replayed) call
                atomicExch(&g_count, 0u);
                atomicExch(reinterpret_cast<unsigned long long*>(&g_firing), 0ull);
            }
        }
    }
}

extern "C" void kernel_launch(void* const* d_in, const int* in_sizes, int n_in,
                              void* d_out, int out_size)
{
    // inputs: [0]=t(1), [1]=y(2N), [2]=gsyn(1), [3]=Isyn(1)
    const float* y    = (const float*)d_in[1];
    const float* gsyn = (const float*)d_in[2];
    const float* isyn = (const float*)d_in[3];
    float* out = (float*)d_out;
    const int n = in_sizes[1] / 2;

    const int nblocks = (n + TILE - 1) / TILE;
    main_kernel<<<nblocks, BLOCK>>>(y, gsyn, isyn, out, n);
}